// round 3
// baseline (speedup 1.0000x reference)
#include <cuda_runtime.h>

// DynamicUpsamplingFilter:
//   x:       (4, 3, 180, 320) f32
//   filters: (4, 25, 16, 180, 320) f32
//   out:     (4, 48, 180, 320) f32
//   out[n, c*16+u, h, w] = sum_p x_pad[n, c, h+p/5-2, w+p%5-2] * filters[n, p, u, h, w]

#define NN 4
#define CC 3
#define HH 180
#define WW 320
#define UU 16
#define KH 5
#define KW 5
#define PP (KH*KW)
#define TILE_W 64
#define SROW 68   // TILE_W + 4 (halo)

#define CP_ASYNC_CG(smem_u32, gptr) \
    asm volatile("cp.async.cg.shared.global [%0], [%1], 16;\n" :: "r"(smem_u32), "l"(gptr))
#define CP_COMMIT() asm volatile("cp.async.commit_group;\n" ::: "memory")
#define CP_WAIT(n)  asm volatile("cp.async.wait_group %0;\n" :: "n"(n) : "memory")

__global__ void __launch_bounds__(256, 4)
duf_kernel(const float* __restrict__ x,
           const float* __restrict__ filters,
           float* __restrict__ out) {
    // Block: one (n, h, w-tile of 64). 256 threads = 16 u x 16 w-quads.
    __shared__ float sx[CC][KH][SROW];              // 4080 B
    __shared__ float fbuf[2][KW][UU][TILE_W];       // 2 x 20480 B row buffers

    const int wq = threadIdx.x & 15;
    const int u  = threadIdx.x >> 4;
    const int wb = blockIdx.x * TILE_W;
    const int h  = blockIdx.y;
    const int n  = blockIdx.z;

    const int w0 = wb + wq * 4;
    const float* fp = filters + ((((size_t)n * PP) * UU + u) * HH + h) * WW + w0;
    const size_t PS = (size_t)UU * HH * WW;  // p-plane stride (elements)

    // Per-thread smem slot base addresses (u32 shared-space)
    unsigned sbase = (unsigned)__cvta_generic_to_shared(&fbuf[0][0][u][wq * 4]);
    const unsigned JSTRIDE = UU * TILE_W * 4;        // bytes between j planes
    const unsigned BSTRIDE = KW * UU * TILE_W * 4;   // bytes between buffers

    // ---- prologue: stage rows 0 and 1 via cp.async ----
    #pragma unroll
    for (int j = 0; j < KW; ++j)
        CP_ASYNC_CG(sbase + j * JSTRIDE, fp + (size_t)j * PS);
    CP_COMMIT();
    #pragma unroll
    for (int j = 0; j < KW; ++j)
        CP_ASYNC_CG(sbase + BSTRIDE + j * JSTRIDE, fp + (size_t)(KW + j) * PS);
    CP_COMMIT();

    // ---- fill shared x tile (overlaps with the async filter loads) ----
    for (int e = threadIdx.x; e < CC * KH * SROW; e += 256) {
        int pos = e % SROW;
        int t   = e / SROW;
        int i   = t % KH;
        int c   = t / KH;
        int col = wb + pos - 2;
        int row = h + i - 2;
        float v = 0.0f;
        if ((unsigned)col < WW && (unsigned)row < HH)
            v = x[((n * CC + c) * HH + row) * WW + col];
        sx[c][i][pos] = v;
    }
    __syncthreads();

    float4 acc[CC];
    #pragma unroll
    for (int c = 0; c < CC; ++c) acc[c] = make_float4(0.f, 0.f, 0.f, 0.f);

    const float* fread = &fbuf[0][0][u][wq * 4];

    #pragma unroll
    for (int i = 0; i < KH; ++i) {
        // wait for row i's group: with row i+1 (and maybe i+2 not yet issued)
        // pending, allow exactly 1 outstanding group.
        if (i < KH - 1) { CP_WAIT(1); } else { CP_WAIT(0); }

        const int b = i & 1;

        // read this thread's 5 staged float4s for row i
        float4 f[KW];
        #pragma unroll
        for (int j = 0; j < KW; ++j)
            f[j] = *reinterpret_cast<const float4*>(
                fread + (size_t)(b * KW + j) * (UU * TILE_W));

        // immediately refill this buffer with row i+2
        if (i < KH - 2) {
            #pragma unroll
            for (int j = 0; j < KW; ++j)
                CP_ASYNC_CG(sbase + b * BSTRIDE + j * JSTRIDE,
                            fp + (size_t)((i + 2) * KW + j) * PS);
            CP_COMMIT();
        }

        #pragma unroll
        for (int c = 0; c < CC; ++c) {
            const float4 a = *reinterpret_cast<const float4*>(&sx[c][i][wq * 4]);
            const float4 bb = *reinterpret_cast<const float4*>(&sx[c][i][wq * 4 + 4]);
            const float pr[8] = {a.x, a.y, a.z, a.w, bb.x, bb.y, bb.z, bb.w};
            #pragma unroll
            for (int j = 0; j < KW; ++j) {
                acc[c].x = fmaf(pr[j + 0], f[j].x, acc[c].x);
                acc[c].y = fmaf(pr[j + 1], f[j].y, acc[c].y);
                acc[c].z = fmaf(pr[j + 2], f[j].z, acc[c].z);
                acc[c].w = fmaf(pr[j + 3], f[j].w, acc[c].w);
            }
        }
    }

    // ---- store: out[n, c*16+u, h, w0..w0+3] ----
    #pragma unroll
    for (int c = 0; c < CC; ++c) {
        float4* optr = reinterpret_cast<float4*>(
            out + ((((size_t)n * (CC * UU)) + c * UU + u) * HH + h) * WW + w0);
        __stcs(optr, acc[c]);
    }
}

extern "C" void kernel_launch(void* const* d_in, const int* in_sizes, int n_in,
                              void* d_out, int out_size) {
    const float* x       = (const float*)d_in[0];
    const float* filters = (const float*)d_in[1];
    float* out           = (float*)d_out;

    dim3 grid(WW / TILE_W, HH, NN);  // (5, 180, 4) = 3600 blocks
    dim3 block(256);
    duf_kernel<<<grid, block>>>(x, filters, out);
}

// round 4
// speedup vs baseline: 1.0036x; 1.0036x over previous
#include <cuda_runtime.h>

// DynamicUpsamplingFilter:
//   x:       (4, 3, 180, 320) f32
//   filters: (4, 25, 16, 180, 320) f32
//   out:     (4, 48, 180, 320) f32
//   out[n, c*16+u, h, w] = sum_p x_pad[n, c, h+p/5-2, w+p%5-2] * filters[n, p, u, h, w]

#define NN 4
#define CC 3
#define HH 180
#define WW 320
#define UU 16
#define KH 5
#define KW 5
#define PP (KH*KW)
#define TILE_W 64
#define SROW 68   // TILE_W + 4 (halo)

#define CP_ASYNC_CG(smem_u32, gptr) \
    asm volatile("cp.async.cg.shared.global [%0], [%1], 16;\n" :: "r"(smem_u32), "l"(gptr))
#define CP_COMMIT() asm volatile("cp.async.commit_group;\n" ::: "memory")
#define CP_WAIT(n)  asm volatile("cp.async.wait_group %0;\n" :: "n"(n) : "memory")

__global__ void __launch_bounds__(256, 5)
duf_kernel(const float* __restrict__ x,
           const float* __restrict__ filters,
           float* __restrict__ out) {
    // Block: one (n, h, w-tile of 64). 256 threads = 16 u x 16 w-quads.
    __shared__ float sx[CC][KH][SROW];           // 4080 B
    __shared__ float fbuf[2][KW][UU][TILE_W];    // 40960 B (2 row buffers)
    // total 45040 B/CTA -> 5 CTAs/SM

    const int wq = threadIdx.x & 15;
    const int u  = threadIdx.x >> 4;
    const int wb = blockIdx.x * TILE_W;
    const int h  = blockIdx.y;
    const int n  = blockIdx.z;

    const int w0 = wb + wq * 4;
    const float* fp = filters + ((((size_t)n * PP) * UU + u) * HH + h) * WW + w0;
    const size_t PS = (size_t)UU * HH * WW;  // p-plane stride (elements)

    // per-thread smem slot (16B) addresses
    unsigned sbase = (unsigned)__cvta_generic_to_shared(&fbuf[0][0][u][wq * 4]);
    const unsigned JSTRIDE = UU * TILE_W * 4;        // bytes between j planes
    const unsigned BSTRIDE = KW * UU * TILE_W * 4;   // bytes between buffers

    // ---- prologue: stage rows 0 and 1 ----
    #pragma unroll
    for (int j = 0; j < KW; ++j)
        CP_ASYNC_CG(sbase + j * JSTRIDE, fp + (size_t)j * PS);
    CP_COMMIT();
    #pragma unroll
    for (int j = 0; j < KW; ++j)
        CP_ASYNC_CG(sbase + BSTRIDE + j * JSTRIDE, fp + (size_t)(KW + j) * PS);
    CP_COMMIT();

    // ---- fill shared x tile (overlaps the async filter loads) ----
    for (int e = threadIdx.x; e < CC * KH * SROW; e += 256) {
        int pos = e % SROW;
        int t   = e / SROW;
        int i   = t % KH;
        int c   = t / KH;
        int col = wb + pos - 2;
        int row = h + i - 2;
        float v = 0.0f;
        if ((unsigned)col < WW && (unsigned)row < HH)
            v = x[((n * CC + c) * HH + row) * WW + col];
        sx[c][i][pos] = v;
    }
    __syncthreads();

    float4 acc[CC];
    #pragma unroll
    for (int c = 0; c < CC; ++c) acc[c] = make_float4(0.f, 0.f, 0.f, 0.f);

    const float* fread = &fbuf[0][0][u][wq * 4];

    #pragma unroll
    for (int i = 0; i < KH; ++i) {
        if (i < KH - 1) { CP_WAIT(1); } else { CP_WAIT(0); }
        const int b = i & 1;

        // c-outer passes: re-read staged filters from smem each pass.
        // Keeps live registers low (no f[5] float4 array held across the row).
        #pragma unroll
        for (int c = 0; c < CC; ++c) {
            const float4 a  = *reinterpret_cast<const float4*>(&sx[c][i][wq * 4]);
            const float4 bb = *reinterpret_cast<const float4*>(&sx[c][i][wq * 4 + 4]);
            const float pr[8] = {a.x, a.y, a.z, a.w, bb.x, bb.y, bb.z, bb.w};
            #pragma unroll
            for (int j = 0; j < KW; ++j) {
                const float4 f = *reinterpret_cast<const float4*>(
                    fread + (size_t)(b * KW + j) * (UU * TILE_W));
                acc[c].x = fmaf(pr[j + 0], f.x, acc[c].x);
                acc[c].y = fmaf(pr[j + 1], f.y, acc[c].y);
                acc[c].z = fmaf(pr[j + 2], f.z, acc[c].z);
                acc[c].w = fmaf(pr[j + 3], f.w, acc[c].w);
            }
        }

        // refill this buffer with row i+2 (per-thread slots; reads above are
        // register-complete long before the async data can land)
        if (i < KH - 2) {
            #pragma unroll
            for (int j = 0; j < KW; ++j)
                CP_ASYNC_CG(sbase + b * BSTRIDE + j * JSTRIDE,
                            fp + (size_t)((i + 2) * KW + j) * PS);
            CP_COMMIT();
        }
    }

    // ---- store: out[n, c*16+u, h, w0..w0+3] ----
    #pragma unroll
    for (int c = 0; c < CC; ++c) {
        float4* optr = reinterpret_cast<float4*>(
            out + ((((size_t)n * (CC * UU)) + c * UU + u) * HH + h) * WW + w0);
        __stcs(optr, acc[c]);
    }
}

extern "C" void kernel_launch(void* const* d_in, const int* in_sizes, int n_in,
                              void* d_out, int out_size) {
    const float* x       = (const float*)d_in[0];
    const float* filters = (const float*)d_in[1];
    float* out           = (float*)d_out;

    dim3 grid(WW / TILE_W, HH, NN);  // (5, 180, 4) = 3600 blocks
    dim3 block(256);
    duf_kernel<<<grid, block>>>(x, filters, out);
}

// round 5
// speedup vs baseline: 1.1286x; 1.1246x over previous
#include <cuda_runtime.h>

// DynamicUpsamplingFilter:
//   x:       (4, 3, 180, 320) f32
//   filters: (4, 25, 16, 180, 320) f32
//   out:     (4, 48, 180, 320) f32
//   out[n, c*16+u, h, w] = sum_p x_pad[n, c, h+p/5-2, w+p%5-2] * filters[n, p, u, h, w]

#define NN 4
#define CC 3
#define HH 180
#define WW 320
#define UU 16
#define KH 5
#define KW 5
#define PP (KH*KW)
#define TILE_W 64
#define SROW 68   // TILE_W + 4 (halo)

__global__ void __launch_bounds__(256, 4)
duf_kernel(const float* __restrict__ x,
           const float* __restrict__ filters,
           float* __restrict__ out) {
    // Block: one (n, h, w-tile of 64). 256 threads = 16 u-values x 16 w-quads.
    __shared__ float sx[CC][KH][SROW];  // 4080 B

    const int wq = threadIdx.x & 15;
    const int u  = threadIdx.x >> 4;
    const int wb = blockIdx.x * TILE_W;
    const int h  = blockIdx.y;
    const int n  = blockIdx.z;

    const int w0 = wb + wq * 4;
    const float* fp = filters + ((((size_t)n * PP) * UU + u) * HH + h) * WW + w0;
    const size_t PS = (size_t)UU * HH * WW;  // p-plane stride (elements)

    // ---- HOIST: issue kernel-row 0's filter loads FIRST, so the DRAM stream
    // is in flight while the x-tile fill + barrier resolve (no dead window
    // at CTA start).
    float4 cur[KW], nxt[KW];
    #pragma unroll
    for (int j = 0; j < KW; ++j)
        cur[j] = __ldcs(reinterpret_cast<const float4*>(fp + (size_t)j * PS));

    // ---- fill shared x tile (3 channels x 5 rows x 68 cols, zero-padded) ----
    for (int e = threadIdx.x; e < CC * KH * SROW; e += 256) {
        int pos = e % SROW;
        int t   = e / SROW;
        int i   = t % KH;
        int c   = t / KH;
        int col = wb + pos - 2;
        int row = h + i - 2;
        float v = 0.0f;
        if ((unsigned)col < WW && (unsigned)row < HH)
            v = x[((n * CC + c) * HH + row) * WW + col];
        sx[c][i][pos] = v;
    }
    __syncthreads();

    float4 acc[CC];
    #pragma unroll
    for (int c = 0; c < CC; ++c) acc[c] = make_float4(0.f, 0.f, 0.f, 0.f);

    #pragma unroll
    for (int i = 0; i < KH; ++i) {
        // prefetch row i+1 while row i computes
        if (i < KH - 1) {
            #pragma unroll
            for (int j = 0; j < KW; ++j)
                nxt[j] = __ldcs(reinterpret_cast<const float4*>(
                    fp + (size_t)((i + 1) * KW + j) * PS));
        }

        #pragma unroll
        for (int c = 0; c < CC; ++c) {
            const float4 a = *reinterpret_cast<const float4*>(&sx[c][i][wq * 4]);
            const float4 b = *reinterpret_cast<const float4*>(&sx[c][i][wq * 4 + 4]);
            const float pr[8] = {a.x, a.y, a.z, a.w, b.x, b.y, b.z, b.w};
            #pragma unroll
            for (int j = 0; j < KW; ++j) {
                acc[c].x = fmaf(pr[j + 0], cur[j].x, acc[c].x);
                acc[c].y = fmaf(pr[j + 1], cur[j].y, acc[c].y);
                acc[c].z = fmaf(pr[j + 2], cur[j].z, acc[c].z);
                acc[c].w = fmaf(pr[j + 3], cur[j].w, acc[c].w);
            }
        }

        if (i < KH - 1) {
            #pragma unroll
            for (int j = 0; j < KW; ++j) cur[j] = nxt[j];
        }
    }

    // ---- store: out[n, c*16+u, h, w0..w0+3] ----
    #pragma unroll
    for (int c = 0; c < CC; ++c) {
        float4* optr = reinterpret_cast<float4*>(
            out + ((((size_t)n * (CC * UU)) + c * UU + u) * HH + h) * WW + w0);
        __stcs(optr, acc[c]);
    }
}

extern "C" void kernel_launch(void* const* d_in, const int* in_sizes, int n_in,
                              void* d_out, int out_size) {
    const float* x       = (const float*)d_in[0];
    const float* filters = (const float*)d_in[1];
    float* out           = (float*)d_out;

    dim3 grid(WW / TILE_W, HH, NN);  // (5, 180, 4) = 3600 blocks
    dim3 block(256);
    duf_kernel<<<grid, block>>>(x, filters, out);
}